// round 5
// baseline (speedup 1.0000x reference)
#include <cuda_runtime.h>
#include <math.h>

// Problem constants
#define B_ 2
#define S_ 2048
#define D_ 1024
#define H_ 16
#define DK_ 64

// ---------------- scratch (no cudaMalloc allowed) ----------------
__device__ float g_q[(size_t)B_ * S_ * D_];
__device__ float g_k[(size_t)B_ * S_ * D_];
__device__ float g_v[(size_t)B_ * S_ * D_];
__device__ float g_ctx[(size_t)B_ * S_ * D_];
// per-row exp partial sums: [z][row][8 bn-tiles * 4 wn] = 32 partials/row
__device__ float g_partial[(size_t)B_ * H_ * S_ * 64];

// ---------------- TF32 helpers ----------------
__device__ __forceinline__ unsigned f2tf32(float x) {
    unsigned r;
    asm("cvt.rna.tf32.f32 %0, %1;" : "=r"(r) : "f"(x));
    return r;
}

__device__ __forceinline__ void mma_tf32(float c[4],
    unsigned a0, unsigned a1, unsigned a2, unsigned a3,
    unsigned b0, unsigned b1)
{
    asm volatile(
        "mma.sync.aligned.m16n8k8.row.col.f32.tf32.tf32.f32 "
        "{%0,%1,%2,%3}, {%4,%5,%6,%7}, {%8,%9}, {%0,%1,%2,%3};"
        : "+f"(c[0]), "+f"(c[1]), "+f"(c[2]), "+f"(c[3])
        : "r"(a0), "r"(a1), "r"(a2), "r"(a3), "r"(b0), "r"(b1));
}

// dynamic smem layout: A 2 bufs of [16][136], B 2 bufs of [16][264]
#define ASH(b,k,r) smA[((b) * 16 + (k)) * 136 + (r)]
#define BSH(b,k,r) smB[((b) * 16 + (k)) * 264 + (r)]
#define SMEM_BYTES ((2 * 16 * 136 + 2 * 16 * 264) * 4)

// store 4 consecutive-k values for row r
#define STS4A(buf, kk, r, v) do { \
    ASH(buf, (kk) + 0, r) = f2tf32((v).x); \
    ASH(buf, (kk) + 1, r) = f2tf32((v).y); \
    ASH(buf, (kk) + 2, r) = f2tf32((v).z); \
    ASH(buf, (kk) + 3, r) = f2tf32((v).w); \
} while (0)
#define STS4B(buf, kk, r, v) do { \
    BSH(buf, (kk) + 0, r) = f2tf32((v).x); \
    BSH(buf, (kk) + 1, r) = f2tf32((v).y); \
    BSH(buf, (kk) + 2, r) = f2tf32((v).z); \
    BSH(buf, (kk) + 3, r) = f2tf32((v).w); \
} while (0)

// ================= projections: C = A @ W^T + bias =================
// Block 128(M) x 256(N), 256 threads, 8 warps as 2(m) x 4(n) of 64x64 tiles.
// grid.z selects (A,W,bias,C) triple -> q/k/v fused in one launch.
__global__ __launch_bounds__(256, 1) void proj_tf32(
    const float* __restrict__ A0, const float* __restrict__ A1, const float* __restrict__ A2,
    const float* __restrict__ W0, const float* __restrict__ W1, const float* __restrict__ W2,
    const float* __restrict__ bi0, const float* __restrict__ bi1, const float* __restrict__ bi2,
    float* __restrict__ C0, float* __restrict__ C1, float* __restrict__ C2)
{
    extern __shared__ unsigned smraw[];
    unsigned* smA = smraw;
    unsigned* smB = smraw + 2 * 16 * 136;

    const int tid  = threadIdx.x;
    const int lane = tid & 31;
    const int wid  = tid >> 5;
    const int wm   = wid & 1;            // 64-row half
    const int wn   = wid >> 1;           // 64-col quarter
    const int bm   = blockIdx.y * 128;
    const int bn   = blockIdx.x * 256;
    const int z    = blockIdx.z;

    const float* A    = (z == 0) ? A0 : (z == 1) ? A1 : A2;
    const float* W    = (z == 0) ? W0 : (z == 1) ? W1 : W2;
    const float* bias = (z == 0) ? bi0 : (z == 1) ? bi1 : bi2;
    float*       C    = (z == 0) ? C0 : (z == 1) ? C1 : C2;

    const int arow = tid & 127;
    const int ak   = (tid >> 7) * 8;
    const float* Ap = A + (size_t)(bm + arow) * D_ + ak;
    const float* Wp = W + (size_t)(bn + tid) * D_;

    float acc[4][8][4];
#pragma unroll
    for (int i = 0; i < 4; i++)
#pragma unroll
        for (int j = 0; j < 8; j++)
#pragma unroll
            for (int e = 0; e < 4; e++) acc[i][j][e] = 0.f;

    float4 a0, a1, w0, w1, w2, w3;
    a0 = *(const float4*)(Ap);
    a1 = *(const float4*)(Ap + 4);
    w0 = *(const float4*)(Wp);
    w1 = *(const float4*)(Wp + 4);
    w2 = *(const float4*)(Wp + 8);
    w3 = *(const float4*)(Wp + 12);
    STS4A(0, ak, arow, a0);
    STS4A(0, ak + 4, arow, a1);
    STS4B(0, 0, tid, w0);
    STS4B(0, 4, tid, w1);
    STS4B(0, 8, tid, w2);
    STS4B(0, 12, tid, w3);
    __syncthreads();

    const int NIT = D_ / 16;
    const int mg  = wm * 64 + (lane >> 2);
    const int ng  = wn * 64 + (lane >> 2);
    const int kl  = lane & 3;

    for (int it = 0; it < NIT; it++) {
        const int cur = it & 1;
        if (it + 1 < NIT) {
            const int k0 = (it + 1) * 16;
            a0 = *(const float4*)(Ap + k0);
            a1 = *(const float4*)(Ap + k0 + 4);
            w0 = *(const float4*)(Wp + k0);
            w1 = *(const float4*)(Wp + k0 + 4);
            w2 = *(const float4*)(Wp + k0 + 8);
            w3 = *(const float4*)(Wp + k0 + 12);
        }
#pragma unroll
        for (int s = 0; s < 2; s++) {
            const int kb = s * 8 + kl;
            unsigned af[4][4];
#pragma unroll
            for (int i = 0; i < 4; i++) {
                af[i][0] = ASH(cur, kb,     mg + i * 16);
                af[i][1] = ASH(cur, kb,     mg + i * 16 + 8);
                af[i][2] = ASH(cur, kb + 4, mg + i * 16);
                af[i][3] = ASH(cur, kb + 4, mg + i * 16 + 8);
            }
#pragma unroll
            for (int j = 0; j < 8; j++) {
                unsigned b0 = BSH(cur, kb,     ng + j * 8);
                unsigned b1 = BSH(cur, kb + 4, ng + j * 8);
#pragma unroll
                for (int i = 0; i < 4; i++)
                    mma_tf32(acc[i][j], af[i][0], af[i][1], af[i][2], af[i][3], b0, b1);
            }
        }
        if (it + 1 < NIT) {
            const int nxt = cur ^ 1;
            STS4A(nxt, ak, arow, a0);
            STS4A(nxt, ak + 4, arow, a1);
            STS4B(nxt, 0, tid, w0);
            STS4B(nxt, 4, tid, w1);
            STS4B(nxt, 8, tid, w2);
            STS4B(nxt, 12, tid, w3);
            __syncthreads();
        }
    }

    const int row0 = bm + wm * 64 + (lane >> 2);
    const int col0 = bn + wn * 64 + (lane & 3) * 2;
    float2 bvj[8];
#pragma unroll
    for (int j = 0; j < 8; j++) bvj[j] = *(const float2*)&bias[col0 + j * 8];

#pragma unroll
    for (int i = 0; i < 4; i++) {
#pragma unroll
        for (int j = 0; j < 8; j++) {
            const int r = row0 + i * 16;
            const int c = col0 + j * 8;
            float2 lo, hi;
            lo.x = acc[i][j][0] + bvj[j].x;
            lo.y = acc[i][j][1] + bvj[j].y;
            hi.x = acc[i][j][2] + bvj[j].x;
            hi.y = acc[i][j][3] + bvj[j].y;
            *(float2*)&C[(size_t)r * D_ + c]       = lo;
            *(float2*)&C[(size_t)(r + 8) * D_ + c] = hi;
        }
    }
}

// ================= QK^T -> exp(scale*s) + row partial sums =================
// Per (b,h): attn[2048,2048] tile 128x256, 8 warps of 64x64, K=64.
__global__ __launch_bounds__(256, 1) void qk_tf32(
    const float* __restrict__ Qg, const float* __restrict__ Kg,
    float* __restrict__ attn, float* __restrict__ partial)
{
    extern __shared__ unsigned smraw[];
    unsigned* smA = smraw;
    unsigned* smB = smraw + 2 * 16 * 136;

    const int tid  = threadIdx.x;
    const int lane = tid & 31;
    const int wid  = tid >> 5;
    const int wm   = wid & 1;
    const int wn   = wid >> 1;
    const int bm   = blockIdx.y * 128;
    const int bn   = blockIdx.x * 256;
    const int z    = blockIdx.z;
    const int zb   = z >> 4, zh = z & 15;
    const size_t base = (size_t)zb * S_ * D_ + (size_t)zh * DK_;

    const int arow = tid & 127;
    const int ak   = (tid >> 7) * 8;
    const float* Ap = Qg + base + (size_t)(bm + arow) * D_ + ak;
    const float* Bp = Kg + base + (size_t)(bn + tid) * D_;

    float acc[4][8][4];
#pragma unroll
    for (int i = 0; i < 4; i++)
#pragma unroll
        for (int j = 0; j < 8; j++)
#pragma unroll
            for (int e = 0; e < 4; e++) acc[i][j][e] = 0.f;

    float4 a0, a1, w0, w1, w2, w3;
    a0 = *(const float4*)(Ap);
    a1 = *(const float4*)(Ap + 4);
    w0 = *(const float4*)(Bp);
    w1 = *(const float4*)(Bp + 4);
    w2 = *(const float4*)(Bp + 8);
    w3 = *(const float4*)(Bp + 12);
    STS4A(0, ak, arow, a0);
    STS4A(0, ak + 4, arow, a1);
    STS4B(0, 0, tid, w0);
    STS4B(0, 4, tid, w1);
    STS4B(0, 8, tid, w2);
    STS4B(0, 12, tid, w3);
    __syncthreads();

    const int NIT = DK_ / 16;   // 4
    const int mg  = wm * 64 + (lane >> 2);
    const int ng  = wn * 64 + (lane >> 2);
    const int kl  = lane & 3;

    for (int it = 0; it < NIT; it++) {
        const int cur = it & 1;
        if (it + 1 < NIT) {
            const int k0 = (it + 1) * 16;
            a0 = *(const float4*)(Ap + k0);
            a1 = *(const float4*)(Ap + k0 + 4);
            w0 = *(const float4*)(Bp + k0);
            w1 = *(const float4*)(Bp + k0 + 4);
            w2 = *(const float4*)(Bp + k0 + 8);
            w3 = *(const float4*)(Bp + k0 + 12);
        }
#pragma unroll
        for (int s = 0; s < 2; s++) {
            const int kb = s * 8 + kl;
            unsigned af[4][4];
#pragma unroll
            for (int i = 0; i < 4; i++) {
                af[i][0] = ASH(cur, kb,     mg + i * 16);
                af[i][1] = ASH(cur, kb,     mg + i * 16 + 8);
                af[i][2] = ASH(cur, kb + 4, mg + i * 16);
                af[i][3] = ASH(cur, kb + 4, mg + i * 16 + 8);
            }
#pragma unroll
            for (int j = 0; j < 8; j++) {
                unsigned b0 = BSH(cur, kb,     ng + j * 8);
                unsigned b1 = BSH(cur, kb + 4, ng + j * 8);
#pragma unroll
                for (int i = 0; i < 4; i++)
                    mma_tf32(acc[i][j], af[i][0], af[i][1], af[i][2], af[i][3], b0, b1);
            }
        }
        if (it + 1 < NIT) {
            const int nxt = cur ^ 1;
            STS4A(nxt, ak, arow, a0);
            STS4A(nxt, ak + 4, arow, a1);
            STS4B(nxt, 0, tid, w0);
            STS4B(nxt, 4, tid, w1);
            STS4B(nxt, 8, tid, w2);
            STS4B(nxt, 12, tid, w3);
            __syncthreads();
        }
    }

    // exp epilogue + partial row sums (32 per row: 8 bn-tiles x 4 wn)
    float* Cp = attn + (size_t)z * S_ * S_;
    const int rl   = wm * 64 + (lane >> 2);
    const int col0 = bn + wn * 64 + (lane & 3) * 2;

#pragma unroll
    for (int i = 0; i < 4; i++) {
        const int rlo = bm + rl + i * 16;
        const int rhi = rlo + 8;
        float pl = 0.f, ph = 0.f;
#pragma unroll
        for (int j = 0; j < 8; j++) {
            float e0 = __expf(acc[i][j][0] * 0.125f);
            float e1 = __expf(acc[i][j][1] * 0.125f);
            float e2 = __expf(acc[i][j][2] * 0.125f);
            float e3 = __expf(acc[i][j][3] * 0.125f);
            float2 lo; lo.x = e0; lo.y = e1;
            float2 hi; hi.x = e2; hi.y = e3;
            *(float2*)&Cp[(size_t)rlo * S_ + col0 + j * 8] = lo;
            *(float2*)&Cp[(size_t)rhi * S_ + col0 + j * 8] = hi;
            pl += e0 + e1;
            ph += e2 + e3;
        }
        pl += __shfl_xor_sync(0xffffffffu, pl, 1);
        pl += __shfl_xor_sync(0xffffffffu, pl, 2);
        ph += __shfl_xor_sync(0xffffffffu, ph, 1);
        ph += __shfl_xor_sync(0xffffffffu, ph, 2);
        if ((lane & 3) == 0) {
            partial[((size_t)z * S_ + rlo) * 32 + blockIdx.x * 4 + wn] = pl;
            partial[((size_t)z * S_ + rhi) * 32 + blockIdx.x * 4 + wn] = ph;
        }
    }
}

// ================= PV: normalize attn in place + ctx = P @ V =================
__device__ __forceinline__ void sts4p(unsigned (*s)[136], int k, int r, float4 v) {
    s[k + 0][r] = f2tf32(v.x);
    s[k + 1][r] = f2tf32(v.y);
    s[k + 2][r] = f2tf32(v.z);
    s[k + 3][r] = f2tf32(v.w);
}

__global__ __launch_bounds__(256, 2) void pv_tf32(
    float* __restrict__ attn, const float* __restrict__ Vg,
    float* __restrict__ ctx, const float* __restrict__ partial)
{
    __shared__ unsigned Ps[2][16][136];
    __shared__ unsigned Vs[2][16][72];
    __shared__ float s_inv[128];

    const int tid  = threadIdx.x;
    const int lane = tid & 31;
    const int wid  = tid >> 5;
    const int wm   = wid & 3;         // 32-row quarter
    const int wn   = wid >> 2;        // 32-col half
    const int bm   = blockIdx.x * 128;
    const int z    = blockIdx.y;
    const int zb   = z >> 4, zh = z & 15;

    // ---- prologue: per-row inverse sums (32 partials per row) ----
    {
        const int r = tid >> 1;
        const float* pp = partial + ((size_t)z * S_ + bm + r) * 32 + (tid & 1) * 16;
        float s = 0.f;
#pragma unroll
        for (int f = 0; f < 4; f++) {
            float4 u = ((const float4*)pp)[f];
            s += (u.x + u.y) + (u.z + u.w);
        }
        s += __shfl_xor_sync(0xffffffffu, s, 1);
        if (!(tid & 1)) s_inv[r] = 1.f / s;
    }
    __syncthreads();

    const int prow = tid >> 1;
    const int pk   = (tid & 1) * 8;
    float* P = attn + (size_t)z * S_ * S_ + (size_t)(bm + prow) * S_ + pk;
    const float inv = s_inv[prow];

    const int vr = tid >> 4;
    const int vc = (tid & 15) * 4;
    const float* Vp = Vg + (size_t)zb * S_ * D_ + (size_t)zh * DK_
                      + (size_t)vr * D_ + vc;

    float acc[2][4][4];
#pragma unroll
    for (int i = 0; i < 2; i++)
#pragma unroll
        for (int j = 0; j < 4; j++)
#pragma unroll
            for (int e = 0; e < 4; e++) acc[i][j][e] = 0.f;

    float4 p0, p1, vv;
    p0 = *(const float4*)(P);
    p1 = *(const float4*)(P + 4);
    p0.x *= inv; p0.y *= inv; p0.z *= inv; p0.w *= inv;
    p1.x *= inv; p1.y *= inv; p1.z *= inv; p1.w *= inv;
    *(float4*)(P)     = p0;
    *(float4*)(P + 4) = p1;
    vv = *(const float4*)(Vp);
    sts4p(Ps[0], pk, prow, p0);
    sts4p(Ps[0], pk + 4, prow, p1);
    Vs[0][vr][vc + 0] = f2tf32(vv.x);
    Vs[0][vr][vc + 1] = f2tf32(vv.y);
    Vs[0][vr][vc + 2] = f2tf32(vv.z);
    Vs[0][vr][vc + 3] = f2tf32(vv.w);
    __syncthreads();

    const int NIT = S_ / 16;
    const int mg  = wm * 32 + (lane >> 2);
    const int ng  = wn * 32 + (lane >> 2);
    const int kl  = lane & 3;

    for (int it = 0; it < NIT; it++) {
        const int cur = it & 1;
        if (it + 1 < NIT) {
            const int k0 = (it + 1) * 16;
            p0 = *(const float4*)(P + k0);
            p1 = *(const float4*)(P + k0 + 4);
            p0.x *= inv; p0.y *= inv; p0.z *= inv; p0.w *= inv;
            p1.x *= inv; p1.y *= inv; p1.z *= inv; p1.w *= inv;
            *(float4*)(P + k0)     = p0;
            *(float4*)(P + k0 + 4) = p1;
            vv = *(const float4*)(Vp + (size_t)k0 * D_);
        }
#pragma unroll
        for (int s = 0; s < 2; s++) {
            const int kb = s * 8 + kl;
            unsigned af[2][4];
#pragma unroll
            for (int i = 0; i < 2; i++) {
                af[i][0] = Ps[cur][kb    ][mg + i * 16];
                af[i][1] = Ps[cur][kb    ][mg + i * 16 + 8];
                af[i][2] = Ps[cur][kb + 4][mg + i * 16];
                af[i][3] = Ps[cur][kb + 4][mg + i * 16 + 8];
            }
            unsigned bf[4][2];
#pragma unroll
            for (int j = 0; j < 4; j++) {
                bf[j][0] = Vs[cur][kb    ][ng + j * 8];
                bf[j][1] = Vs[cur][kb + 4][ng + j * 8];
            }
#pragma unroll
            for (int j = 0; j < 4; j++)
#pragma unroll
                for (int i = 0; i < 2; i++)
                    mma_tf32(acc[i][j], af[i][0], af[i][1], af[i][2], af[i][3],
                             bf[j][0], bf[j][1]);
        }
        if (it + 1 < NIT) {
            const int nxt = cur ^ 1;
            sts4p(Ps[nxt], pk, prow, p0);
            sts4p(Ps[nxt], pk + 4, prow, p1);
            Vs[nxt][vr][vc + 0] = f2tf32(vv.x);
            Vs[nxt][vr][vc + 1] = f2tf32(vv.y);
            Vs[nxt][vr][vc + 2] = f2tf32(vv.z);
            Vs[nxt][vr][vc + 3] = f2tf32(vv.w);
            __syncthreads();
        }
    }

    float* Cc = ctx + (size_t)zb * S_ * D_ + (size_t)zh * DK_;
    const int row0 = bm + wm * 32 + (lane >> 2);
    const int col0 = wn * 32 + (lane & 3) * 2;
#pragma unroll
    for (int i = 0; i < 2; i++) {
#pragma unroll
        for (int j = 0; j < 4; j++) {
            const int r = row0 + i * 16;
            const int c = col0 + j * 8;
            float2 lo, hi;
            lo.x = acc[i][j][0]; lo.y = acc[i][j][1];
            hi.x = acc[i][j][2]; hi.y = acc[i][j][3];
            *(float2*)&Cc[(size_t)r * D_ + c]       = lo;
            *(float2*)&Cc[(size_t)(r + 8) * D_ + c] = hi;
        }
    }
}

// ---------------- launch ----------------
extern "C" void kernel_launch(void* const* d_in, const int* in_sizes, int n_in,
                              void* d_out, int out_size)
{
    const float* query = (const float*)d_in[0];
    const float* key   = (const float*)d_in[1];
    const float* value = (const float*)d_in[2];
    const float* Wq    = (const float*)d_in[3];
    const float* bq    = (const float*)d_in[4];
    const float* Wk    = (const float*)d_in[5];
    const float* bk    = (const float*)d_in[6];
    const float* Wv    = (const float*)d_in[7];
    const float* bv    = (const float*)d_in[8];
    const float* Wo    = (const float*)d_in[9];
    const float* bo    = (const float*)d_in[10];

    float* out  = (float*)d_out;                          // (B,S,D)
    float* attn = out + (size_t)B_ * S_ * D_;             // (B,H,S,S)

    float *q, *k, *v, *ctx, *part;
    cudaGetSymbolAddress((void**)&q,    g_q);
    cudaGetSymbolAddress((void**)&k,    g_k);
    cudaGetSymbolAddress((void**)&v,    g_v);
    cudaGetSymbolAddress((void**)&ctx,  g_ctx);
    cudaGetSymbolAddress((void**)&part, g_partial);

    cudaFuncSetAttribute(proj_tf32, cudaFuncAttributeMaxDynamicSharedMemorySize, SMEM_BYTES);
    cudaFuncSetAttribute(qk_tf32,   cudaFuncAttributeMaxDynamicSharedMemorySize, SMEM_BYTES);

    // q/k/v projections fused: grid.z = 3
    dim3 pgrid(D_ / 256, (B_ * S_) / 128, 3);
    proj_tf32<<<pgrid, 256, SMEM_BYTES>>>(query, key, value,
                                          Wq, Wk, Wv, bq, bk, bv,
                                          q, k, v);

    // QK^T -> exp(scores) + row partial sums
    dim3 qkgrid(S_ / 256, S_ / 128, B_ * H_);
    qk_tf32<<<qkgrid, 256, SMEM_BYTES>>>(q, k, attn, part);

    // normalize attn in place + ctx = P @ V
    dim3 pvgrid(S_ / 128, B_ * H_);
    pv_tf32<<<pvgrid, 256>>>(attn, v, ctx, part);

    // output projection (single triple)
    dim3 ogrid(D_ / 256, (B_ * S_) / 128, 1);
    proj_tf32<<<ogrid, 256, SMEM_BYTES>>>(ctx, ctx, ctx,
                                          Wo, Wo, Wo, bo, bo, bo,
                                          out, out, out);
}